// round 15
// baseline (speedup 1.0000x reference)
#include <cuda_runtime.h>
#include <math.h>
#include <cstdint>

// ---------------------------------------------------------------------------
// Problem constants
// ---------------------------------------------------------------------------
#define BB    4
#define SEQ   3072
#define DIMC  768
#define NH    3
#define HDIM  256
#define DD    262
#define BHN   12
#define HD3   786
#define HD3P  788          // padded to 16B-aligned rows
#define NPART (SEQ / 128)  // 24 partial sums per row/col

// ---------------------------------------------------------------------------
// Scratch (device globals: sanctioned alloc-free scratch)
// ---------------------------------------------------------------------------
static __device__ float g_qkvP[(size_t)3 * BHN * SEQ * HDIM];  // [s][bh][n][d] (tf32-rounded)
static __device__ float g_attn[(size_t)BHN * SEQ * SEQ];       // attnT: [bh][m][n] = e^2 (tf32)
static __device__ float g_vcatR[(size_t)BHN * DD * SEQ];       // [bh][e][n] * rinv[n] (rounded)
static __device__ float g_vcatC[(size_t)BHN * DD * SEQ];       // [bh][e][m] * cinv[m] (rounded)
static __device__ float g_f1  [(size_t)BHN * DD * SEQ];        // [bh][d][m] (rounded, no cinv)
static __device__ float g_fundT[(size_t)BB * DD * HD3P];       // padded ld (rounded)
static __device__ float g_xr[(size_t)BB * SEQ * DIMC];         // rounded x
static __device__ float g_wqkvr[(size_t)3 * DIMC * DIMC];      // rounded W_qkv
static __device__ float g_wpfr[(size_t)DIMC * HD3P];           // rounded+padded W_pf
static __device__ float g_rinv[BHN * SEQ];                     // 1/col-sum (per n)
static __device__ float g_cinv[BHN * SEQ];                     // 1/row-sum (per m)
static __device__ float g_csump[(size_t)NPART * BHN * SEQ];    // partial row-sums (per m)
static __device__ float g_rsump[(size_t)NPART * BHN * SEQ];    // partial col-sums (per n)

// ---------------------------------------------------------------------------
// Helpers (plain sm_80-era PTX; nothing "a"-gated)
// ---------------------------------------------------------------------------
__device__ __forceinline__ uint32_t smem_u32(const void* p) {
    uint32_t a;
    asm("{ .reg .u64 t; cvta.to.shared.u64 t, %1; cvt.u32.u64 %0, t; }" : "=r"(a) : "l"(p));
    return a;
}
__device__ __forceinline__ float cvt_tf32(float x) {
    float y; asm("cvt.rna.tf32.f32 %0, %1;" : "=f"(y) : "f"(x)); return y;
}
__device__ __forceinline__ void cp16(uint32_t dst, const void* src, int srcbytes) {
    asm volatile("cp.async.cg.shared.global [%0], [%1], 16, %2;"
                 :: "r"(dst), "l"(src), "r"(srcbytes));
}
__device__ __forceinline__ void cp_commit() { asm volatile("cp.async.commit_group;"); }
__device__ __forceinline__ void cp_wait1()  { asm volatile("cp.async.wait_group 1;"); }
__device__ __forceinline__ void cp_wait0()  { asm volatile("cp.async.wait_group 0;"); }

#define LDSM_X4(r, addr) \
    asm volatile("ldmatrix.sync.aligned.m8n8.x4.shared.b16 {%0,%1,%2,%3}, [%4];" \
        : "=r"((r)[0]), "=r"((r)[1]), "=r"((r)[2]), "=r"((r)[3]) : "r"(addr))

#define MMA_TF32(c, a, b0v, b1v) \
    asm volatile("mma.sync.aligned.m16n8k8.row.col.f32.tf32.tf32.f32 " \
        "{%0,%1,%2,%3}, {%4,%5,%6,%7}, {%8,%9}, {%0,%1,%2,%3};" \
        : "+f"((c)[0]), "+f"((c)[1]), "+f"((c)[2]), "+f"((c)[3]) \
        : "r"((a)[0]), "r"((a)[1]), "r"((a)[2]), "r"((a)[3]), "r"(b0v), "r"(b1v))

// ---------------------------------------------------------------------------
// tf32 tensor-core GEMM, cp.async 3-stage pipeline.
// C[i,j] = alpha * sum_k A(i,k)*B(j,k); operands PRE-ROUNDED to tf32 in gmem.
// CTA tile 128x128, K-tile 32, 128 threads = 4 warps (2x2), 64x64 warptile.
// Per ks: 4 A-LDSM + 4 B-LDSM -> 32 MMA (128 B smem/MMA, was 192).
// EPI 0: plain store; EPI 1: QKV scatter; EPI 2: +bias[j];
// EPI 3: store tf32(e^2), e=exp(v*alpha), + per-CTA row/col partial sums of e;
// EPI 4: transposed scatter into fundT[b][e][h*DD+d].
// RND: tf32-round output.
// ---------------------------------------------------------------------------
#define STAGE_STRIDE 32768u
static constexpr unsigned SMEM_TOTAL = 3 * STAGE_STRIDE;   // 96 KB

__device__ __forceinline__ void issue_stage(
    const float* __restrict__ A, const float* __restrict__ B, uint32_t sb, int kt,
    int i0, int j0, int M, int N, int K, int lda, int ldb, int u, int rs)
{
    const uint32_t aB = sb + (uint32_t)(kt % 3) * STAGE_STRIDE;
    const uint32_t bB = aB + 16384u;
    const int kk  = kt * 32 + u * 4;
    const int rem = K - kk;
    const int bytes = rem >= 4 ? 16 : (rem > 0 ? rem * 4 : 0);
    const uint32_t csw = (uint32_t)(u * 16);
#pragma unroll
    for (int it = 0; it < 8; it++) {
        int r = rs + it * 16;
        uint32_t off = (uint32_t)(r * 128) + (csw ^ (uint32_t)((r & 7) << 4));
        int gia = i0 + r, gib = j0 + r;
        const float* pa = A + (long long)(gia < M ? gia : 0) * lda + kk;
        const float* pb = B + (long long)(gib < N ? gib : 0) * ldb + kk;
        cp16(aB + off, pa, gia < M ? bytes : 0);
        cp16(bB + off, pb, gib < N ? bytes : 0);
    }
    cp_commit();
}

template<int EPI, int RND>
__global__ void __launch_bounds__(128, 2) ca_gemm(
    const float* __restrict__ A, const float* __restrict__ B,
    float* __restrict__ C, const float* __restrict__ bias,
    int M, int N, int K, int lda, int ldb, int ldc,
    long long sA, long long sB, long long sC, float alpha,
    float* __restrict__ csump, float* __restrict__ rsump)
{
    extern __shared__ char smem[];
    const uint32_t sb = smem_u32(smem);

    A += (long long)blockIdx.z * sA;
    B += (long long)blockIdx.z * sB;
    if (EPI != 1) C += (long long)blockIdx.z * sC;
    const int i0 = blockIdx.y * 128;
    const int j0 = blockIdx.x * 128;

    const int tid  = threadIdx.x;
    const int wid  = tid >> 5, lane = tid & 31;
    const int wm   = wid >> 1, wn = wid & 1;      // 2x2 warps, 64x64 each
    const int g    = lane >> 2, tg = lane & 3;
    const int sub  = lane >> 3, l  = lane & 7;
    const int u    = tid & 7,  rs  = tid >> 3;    // staging: chunk, row 0..15

    const int halfA = sub >> 1;
    const int halfB = sub & 1;
    uint32_t laOff[4], la7[4], lbOff[4], lb7[4];
#pragma unroll
    for (int m = 0; m < 4; m++) {
        int r = wm * 64 + m * 16 + (sub & 1) * 8 + l;
        laOff[m] = (uint32_t)(r * 128); la7[m] = (uint32_t)(r & 7);
    }
#pragma unroll
    for (int p = 0; p < 4; p++) {
        int r = wn * 64 + p * 16 + (sub >> 1) * 8 + l;
        lbOff[p] = (uint32_t)(r * 128); lb7[p] = (uint32_t)(r & 7);
    }

    float acc[4][8][4];
#pragma unroll
    for (int m = 0; m < 4; m++)
#pragma unroll
        for (int n = 0; n < 8; n++)
#pragma unroll
            for (int e = 0; e < 4; e++) acc[m][n][e] = 0.f;

    const int nk = (K + 31) / 32;
    issue_stage(A, B, sb, 0, i0, j0, M, N, K, lda, ldb, u, rs);
    if (nk > 1) issue_stage(A, B, sb, 1, i0, j0, M, N, K, lda, ldb, u, rs);

    for (int kt = 0; kt < nk; kt++) {
        if (kt + 1 < nk) cp_wait1(); else cp_wait0();
        __syncthreads();
        if (kt + 2 < nk)
            issue_stage(A, B, sb, kt + 2, i0, j0, M, N, K, lda, ldb, u, rs);

        const uint32_t aB = sb + (uint32_t)(kt % 3) * STAGE_STRIDE;
        const uint32_t bB = aB + 16384u;
#pragma unroll
        for (int ks = 0; ks < 4; ks++) {
            uint32_t af[4][4], bf[4][4];
#pragma unroll
            for (int m = 0; m < 4; m++) {
                uint32_t ch = (uint32_t)(ks * 2 + halfA) ^ la7[m];
                LDSM_X4(af[m], aB + laOff[m] + (ch << 4));
            }
#pragma unroll
            for (int p = 0; p < 4; p++) {
                uint32_t ch = (uint32_t)(ks * 2 + halfB) ^ lb7[p];
                LDSM_X4(bf[p], bB + lbOff[p] + (ch << 4));
            }
#pragma unroll
            for (int m = 0; m < 4; m++) {
#pragma unroll
                for (int n = 0; n < 8; n++)
                    MMA_TF32(acc[m][n], af[m], bf[n >> 1][(n & 1) * 2], bf[n >> 1][(n & 1) * 2 + 1]);
            }
        }
    }

    if (EPI == 3) {
        // ---- softmax-fused epilogue: store tf32(e^2), reduce partial sums of e ----
        __syncthreads();
        float* red = (float*)smem;            // [0:128) row sums, [128:256) col sums
        red[tid] = 0.f; red[tid + 128] = 0.f;
        __syncthreads();

        float colacc[8][2];
#pragma unroll
        for (int n = 0; n < 8; n++) { colacc[n][0] = 0.f; colacc[n][1] = 0.f; }

#pragma unroll
        for (int m = 0; m < 4; m++) {
            int r0 = i0 + wm * 64 + m * 16 + g;
            float rowacc0 = 0.f, rowacc1 = 0.f;
#pragma unroll
            for (int n = 0; n < 8; n++) {
                int gj = j0 + wn * 64 + n * 8 + 2 * tg;
                float e0 = __expf(acc[m][n][0] * alpha);
                float e1 = __expf(acc[m][n][1] * alpha);
                float e2 = __expf(acc[m][n][2] * alpha);
                float e3 = __expf(acc[m][n][3] * alpha);
                *(float2*)&C[(long long)r0 * ldc + gj] =
                    make_float2(cvt_tf32(e0 * e0), cvt_tf32(e1 * e1));
                *(float2*)&C[(long long)(r0 + 8) * ldc + gj] =
                    make_float2(cvt_tf32(e2 * e2), cvt_tf32(e3 * e3));
                rowacc0 += e0 + e1; rowacc1 += e2 + e3;
                colacc[n][0] += e0 + e2; colacc[n][1] += e1 + e3;
            }
            rowacc0 += __shfl_xor_sync(0xffffffffu, rowacc0, 1);
            rowacc0 += __shfl_xor_sync(0xffffffffu, rowacc0, 2);
            rowacc1 += __shfl_xor_sync(0xffffffffu, rowacc1, 1);
            rowacc1 += __shfl_xor_sync(0xffffffffu, rowacc1, 2);
            if (tg == 0) {
                atomicAdd(&red[wm * 64 + m * 16 + g], rowacc0);
                atomicAdd(&red[wm * 64 + m * 16 + g + 8], rowacc1);
            }
        }
#pragma unroll
        for (int n = 0; n < 8; n++) {
            float c0 = colacc[n][0], c1 = colacc[n][1];
            c0 += __shfl_xor_sync(0xffffffffu, c0, 4);
            c0 += __shfl_xor_sync(0xffffffffu, c0, 8);
            c0 += __shfl_xor_sync(0xffffffffu, c0, 16);
            c1 += __shfl_xor_sync(0xffffffffu, c1, 4);
            c1 += __shfl_xor_sync(0xffffffffu, c1, 8);
            c1 += __shfl_xor_sync(0xffffffffu, c1, 16);
            if (g == 0) {
                atomicAdd(&red[128 + wn * 64 + n * 8 + 2 * tg], c0);
                atomicAdd(&red[128 + wn * 64 + n * 8 + 2 * tg + 1], c1);
            }
        }
        __syncthreads();
        const int S = BHN * SEQ;
        csump[(long long)blockIdx.x * S + blockIdx.z * SEQ + i0 + tid] = red[tid];
        rsump[(long long)blockIdx.y * S + blockIdx.z * SEQ + j0 + tid] = red[tid + 128];
        return;
    }

    // ---- standard / scatter epilogues ----
    int bF = 0, hF = 0;
    if (EPI == 4) { bF = blockIdx.z / NH; hF = blockIdx.z - bF * NH; }
#pragma unroll
    for (int m = 0; m < 4; m++) {
        int r0 = i0 + wm * 64 + m * 16 + g;
#pragma unroll
        for (int n = 0; n < 8; n++) {
            int gj = j0 + wn * 64 + n * 8 + 2 * tg;
            if (gj >= N) continue;
            float2 v0 = make_float2(acc[m][n][0] * alpha, acc[m][n][1] * alpha);
            float2 v1 = make_float2(acc[m][n][2] * alpha, acc[m][n][3] * alpha);
            if (EPI == 2) {
                float2 bv = *(const float2*)(bias + gj);
                v0.x += bv.x; v0.y += bv.y; v1.x += bv.x; v1.y += bv.y;
            }
            if (RND) {
                v0.x = cvt_tf32(v0.x); v0.y = cvt_tf32(v0.y);
                v1.x = cvt_tf32(v1.x); v1.y = cvt_tf32(v1.y);
            }
            if (EPI == 1) {
                int s_  = gj / DIMC;
                int rc  = gj - s_ * DIMC;
                int h   = rc >> 8;
                int d   = rc & 255;
#pragma unroll
                for (int hh = 0; hh < 2; hh++) {
                    int gi = r0 + hh * 8;
                    if (gi >= M) continue;
                    int b_ = gi / SEQ, nn = gi - b_ * SEQ;
                    long long dst = ((((long long)s_ * BHN) + (b_ * NH + h)) * SEQ + nn) * HDIM + d;
                    *(float2*)&C[dst] = hh ? v1 : v0;
                }
            } else if (EPI == 4) {
                // fundT[bF][gj(=e)][hF*DD + gi(=d)]
                if (r0 < M) {
                    C[((long long)(bF * DD + gj)) * HD3P + hF * DD + r0] = v0.x;
                    if (gj + 1 < N)
                        C[((long long)(bF * DD + gj + 1)) * HD3P + hF * DD + r0] = v0.y;
                }
                if (r0 + 8 < M) {
                    C[((long long)(bF * DD + gj)) * HD3P + hF * DD + r0 + 8] = v1.x;
                    if (gj + 1 < N)
                        C[((long long)(bF * DD + gj + 1)) * HD3P + hF * DD + r0 + 8] = v1.y;
                }
            } else {
                if (r0 < M)     *(float2*)&C[(long long)r0 * ldc + gj] = v0;
                if (r0 + 8 < M) *(float2*)&C[(long long)(r0 + 8) * ldc + gj] = v1;
            }
        }
    }
}

// ---------------------------------------------------------------------------
// Prep: tf32-round copies of external inputs
// ---------------------------------------------------------------------------
__global__ void round_copy4(const float4* __restrict__ src, float4* __restrict__ dst, int n4)
{
    int i = blockIdx.x * 256 + threadIdx.x;
    if (i >= n4) return;
    float4 v = src[i];
    v.x = cvt_tf32(v.x); v.y = cvt_tf32(v.y); v.z = cvt_tf32(v.z); v.w = cvt_tf32(v.w);
    dst[i] = v;
}

__global__ void pad_round_wpf(const float* __restrict__ W, float* __restrict__ out)
{
    int idx = blockIdx.x * 256 + threadIdx.x;
    if (idx >= DIMC * HD3P) return;
    int o = idx / HD3P, j = idx - o * HD3P;
    out[idx] = (j < HD3) ? cvt_tf32(W[o * HD3 + j]) : 0.f;
}

// ---------------------------------------------------------------------------
// Combine NPART partial sums -> reciprocal
// ---------------------------------------------------------------------------
__global__ void part_comb(const float* __restrict__ part, float* __restrict__ inv)
{
    const int idx = blockIdx.x * 256 + threadIdx.x;
    if (idx >= BHN * SEQ) return;
    float s = 0.f;
#pragma unroll
    for (int p = 0; p < NPART; p++) s += part[(long long)p * (BHN * SEQ) + idx];
    inv[idx] = 1.f / s;
}

// ---------------------------------------------------------------------------
// vcatR[bh][d][n] = v[bh][n][d]*rinv[n];  vcatC[bh][d][n] = v[bh][n][d]*cinv[n]
// (32x32 smem transpose; both outputs tf32-rounded)
// ---------------------------------------------------------------------------
__global__ void build_vcat2(const float* __restrict__ qkvP,
                            const float* __restrict__ rinv, const float* __restrict__ cinv,
                            float* __restrict__ vcatR, float* __restrict__ vcatC)
{
    __shared__ float t[32][33];
    const int bh = blockIdx.z;
    const int n0 = blockIdx.x * 32;
    const int d0 = blockIdx.y * 32;
    const float* src = qkvP + ((long long)(2 * BHN + bh) * SEQ) * HDIM;
#pragma unroll
    for (int k = 0; k < 4; k++) {
        int n = n0 + threadIdx.y + k * 8;
        t[threadIdx.y + k * 8][threadIdx.x] = src[(long long)n * HDIM + d0 + threadIdx.x];
    }
    __syncthreads();
    const int n = n0 + threadIdx.x;
    const float rs = rinv[bh * SEQ + n];
    const float cs = cinv[bh * SEQ + n];
    float* dR = vcatR + (long long)bh * DD * SEQ;
    float* dC = vcatC + (long long)bh * DD * SEQ;
#pragma unroll
    for (int k = 0; k < 4; k++) {
        int d = d0 + threadIdx.y + k * 8;
        float v = t[threadIdx.x][threadIdx.y + k * 8];
        dR[(long long)d * SEQ + n] = cvt_tf32(v * rs);
        dC[(long long)d * SEQ + n] = cvt_tf32(v * cs);
    }
}

// positional rows e = 256..261 of vcatR/vcatC (scaled per-bh)
__global__ void build_pos2(const float* __restrict__ rinv, const float* __restrict__ cinv,
                           float* __restrict__ vcatR, float* __restrict__ vcatC)
{
    const int n  = blockIdx.x * 256 + threadIdx.x;
    const int bh = blockIdx.y;
    int iy = n % 48;
    int ix = n / 48;
    float y = -1.f + 2.f * (float)iy / 47.f;
    float x = -1.f + 2.f * (float)ix / 63.f;
    float p[6] = { y * y, x * x, y * x, y, x, 1.f };
    const float rs = rinv[bh * SEQ + n];
    const float cs = cinv[bh * SEQ + n];
    float* dR = vcatR + (long long)bh * DD * SEQ + n;
    float* dC = vcatC + (long long)bh * DD * SEQ + n;
#pragma unroll
    for (int j = 0; j < 6; j++) {
        dR[(long long)(HDIM + j) * SEQ] = cvt_tf32(p[j] * rs);
        dC[(long long)(HDIM + j) * SEQ] = cvt_tf32(p[j] * cs);
    }
}

// ---------------------------------------------------------------------------
// f1 positional rows: f1[bh][256+j][m] = sum_n vcatR_pos[bh][j][n] * e2[bh][m][n]
// p rows cached in smem (per-bh: rinv-scaled). Grid (SEQ/32, BHN).
// ---------------------------------------------------------------------------
__global__ void __launch_bounds__(256) f1_pos(
    const float* __restrict__ attnf, const float* __restrict__ vcatR,
    float* __restrict__ f1)
{
    __shared__ float ps[6][1024];
    const int bh  = blockIdx.y;
    const int m0  = blockIdx.x * 32;
    const int tid = threadIdx.x, wid = tid >> 5, lane = tid & 31;

    float acc[4][6];
#pragma unroll
    for (int rr = 0; rr < 4; rr++)
#pragma unroll
        for (int j = 0; j < 6; j++) acc[rr][j] = 0.f;

    const float* pbase = vcatR + ((long long)bh * DD + HDIM) * SEQ;

    for (int c = 0; c < 3; c++) {
        const int n0c = c * 1024;
        __syncthreads();
#pragma unroll
        for (int j = 0; j < 6; j++)
            *(float4*)&ps[j][tid * 4] = *(const float4*)(pbase + (long long)j * SEQ + n0c + tid * 4);
        __syncthreads();
#pragma unroll
        for (int rr = 0; rr < 4; rr++) {
            const int m = m0 + wid * 4 + rr;
            const float* arow = attnf + ((long long)bh * SEQ + m) * SEQ + n0c;
#pragma unroll
            for (int q = 0; q < 8; q++) {
                const int nl = lane * 4 + q * 128;
                float4 a = *(const float4*)(arow + nl);
#pragma unroll
                for (int j = 0; j < 6; j++) {
                    float4 p4 = *(const float4*)&ps[j][nl];
                    acc[rr][j] += a.x * p4.x + a.y * p4.y + a.z * p4.z + a.w * p4.w;
                }
            }
        }
    }
#pragma unroll
    for (int rr = 0; rr < 4; rr++) {
        const int m = m0 + wid * 4 + rr;
#pragma unroll
        for (int j = 0; j < 6; j++) {
            float s = acc[rr][j];
            for (int o = 16; o; o >>= 1) s += __shfl_xor_sync(0xffffffffu, s, o);
            if (lane == 0)
                f1[((long long)bh * DD + HDIM + j) * SEQ + m] = cvt_tf32(s);
        }
    }
}

__global__ void zero_pad_fundT(float* __restrict__ fundT)
{
    const int idx = blockIdx.x * 256 + threadIdx.x;
    if (idx >= BB * DD * 2) return;
    int p = idx & 1, row = idx >> 1;
    fundT[(long long)row * HD3P + HD3 + p] = 0.f;
}

// ---------------------------------------------------------------------------
// Launch
// ---------------------------------------------------------------------------
extern "C" void kernel_launch(void* const* d_in, const int* in_sizes, int n_in,
                              void* d_out, int out_size)
{
    const float* x    = (const float*)d_in[0];  // [4,3072,768]
    const float* Wqkv = (const float*)d_in[1];  // [2304,768]
    const float* Wpf  = (const float*)d_in[2];  // [768,786]
    const float* bpf  = (const float*)d_in[3];  // [768]
    float* out = (float*)d_out;                 // [4,262,768]

    float *qkvP, *attn, *vcatR, *vcatC, *f1, *fundT, *xr, *wqkvr, *wpfr;
    float *rinv, *cinv, *csump, *rsump;
    cudaGetSymbolAddress((void**)&qkvP,  g_qkvP);
    cudaGetSymbolAddress((void**)&attn,  g_attn);
    cudaGetSymbolAddress((void**)&vcatR, g_vcatR);
    cudaGetSymbolAddress((void**)&vcatC, g_vcatC);
    cudaGetSymbolAddress((void**)&f1,    g_f1);
    cudaGetSymbolAddress((void**)&fundT, g_fundT);
    cudaGetSymbolAddress((void**)&xr,    g_xr);
    cudaGetSymbolAddress((void**)&wqkvr, g_wqkvr);
    cudaGetSymbolAddress((void**)&wpfr,  g_wpfr);
    cudaGetSymbolAddress((void**)&rinv,  g_rinv);
    cudaGetSymbolAddress((void**)&cinv,  g_cinv);
    cudaGetSymbolAddress((void**)&csump, g_csump);
    cudaGetSymbolAddress((void**)&rsump, g_rsump);

    cudaFuncSetAttribute(ca_gemm<0,1>, cudaFuncAttributeMaxDynamicSharedMemorySize, SMEM_TOTAL);
    cudaFuncSetAttribute(ca_gemm<1,1>, cudaFuncAttributeMaxDynamicSharedMemorySize, SMEM_TOTAL);
    cudaFuncSetAttribute(ca_gemm<2,0>, cudaFuncAttributeMaxDynamicSharedMemorySize, SMEM_TOTAL);
    cudaFuncSetAttribute(ca_gemm<3,0>, cudaFuncAttributeMaxDynamicSharedMemorySize, SMEM_TOTAL);
    cudaFuncSetAttribute(ca_gemm<4,1>, cudaFuncAttributeMaxDynamicSharedMemorySize, SMEM_TOTAL);

    const long long sQ = (long long)SEQ * HDIM;

    // 0) tf32-round external operands
    round_copy4<<<(BB * SEQ * DIMC / 4 + 255) / 256, 256>>>(
        (const float4*)x, (float4*)xr, BB * SEQ * DIMC / 4);
    round_copy4<<<(3 * DIMC * DIMC / 4 + 255) / 256, 256>>>(
        (const float4*)Wqkv, (float4*)wqkvr, 3 * DIMC * DIMC / 4);
    pad_round_wpf<<<(DIMC * HD3P + 255) / 256, 256>>>(Wpf, wpfr);

    // 1) QKV projection, scattered (rounded) to [s][bh][n][d]
    ca_gemm<1,1><<<dim3((3 * DIMC) / 128, (BB * SEQ) / 128, 1), 128, SMEM_TOTAL>>>(
        xr, wqkvr, qkvP, nullptr,
        BB * SEQ, 3 * DIMC, DIMC, DIMC, DIMC, 0, 0, 0, 0, 1.f, nullptr, nullptr);

    // 2) attnT[m][n] = tf32(e^2), e = exp(scale * k_m . q_n); fused partial sums of e
    ca_gemm<3,0><<<dim3(SEQ / 128, SEQ / 128, BHN), 128, SMEM_TOTAL>>>(
        qkvP + (long long)BHN * sQ, qkvP, attn, nullptr,
        SEQ, SEQ, HDIM, HDIM, HDIM, SEQ,
        sQ, sQ, (long long)SEQ * SEQ, 0.0625f, csump, rsump);

    // 3) combine partials -> reciprocals
    part_comb<<<(BHN * SEQ + 255) / 256, 256>>>(csump, cinv);
    part_comb<<<(BHN * SEQ + 255) / 256, 256>>>(rsump, rinv);

    // 4) vcatR/vcatC = scaled transposed v_cat (+ pos rows)
    build_vcat2<<<dim3(SEQ / 32, HDIM / 32, BHN), dim3(32, 8)>>>(qkvP, rinv, cinv, vcatR, vcatC);
    build_pos2<<<dim3(SEQ / 256, BHN), 256>>>(rinv, cinv, vcatR, vcatC);

    // 5) f1 v-rows: f1[d][m] = sum_n vcatR[d][n] * e2[m][n]   (+ pos rows kernel)
    ca_gemm<0,1><<<dim3(SEQ / 128, HDIM / 128, BHN), 128, SMEM_TOTAL>>>(
        vcatR, attn, f1, nullptr,
        HDIM, SEQ, SEQ, SEQ, SEQ, SEQ,
        (long long)DD * SEQ, (long long)SEQ * SEQ, (long long)DD * SEQ, 1.f, nullptr, nullptr);
    f1_pos<<<dim3(SEQ / 32, BHN), 256>>>(attn, vcatR, f1);

    // 6) fund[d][e] = sum_m f1[d][m] * vcatC[e][m], scattered into fundT (EPI4)
    ca_gemm<4,1><<<dim3((DD + 127) / 128, (DD + 127) / 128, BHN), 128, SMEM_TOTAL>>>(
        f1, vcatC, fundT, nullptr,
        DD, DD, SEQ, SEQ, SEQ, 0,
        (long long)DD * SEQ, (long long)DD * SEQ, 0, 1.f, nullptr, nullptr);
    zero_pad_fundT<<<(BB * DD * 2 + 255) / 256, 256>>>(fundT);

    // 7) out[b][e][o] = sum_j fundT[b][e][j] * Wpf[o][j] + bpf[o]
    ca_gemm<2,0><<<dim3(DIMC / 128, (DD + 127) / 128, BB), 128, SMEM_TOTAL>>>(
        fundT, wpfr, out, bpf,
        DD, DIMC, HD3, HD3P, HD3P, DIMC,
        (long long)DD * HD3P, 0, (long long)DD * DIMC, 1.f, nullptr, nullptr);
}

// round 17
// speedup vs baseline: 1.0323x; 1.0323x over previous
#include <cuda_runtime.h>
#include <math.h>
#include <cstdint>

// ---------------------------------------------------------------------------
// Problem constants
// ---------------------------------------------------------------------------
#define BB    4
#define SEQ   3072
#define DIMC  768
#define NH    3
#define HDIM  256
#define DD    262
#define BHN   12
#define HD3   786
#define HD3P  788          // padded to 16B-aligned rows
#define NPART (SEQ / 128)  // 24 partial sums per row/col

// ---------------------------------------------------------------------------
// Scratch (device globals: sanctioned alloc-free scratch)
// ---------------------------------------------------------------------------
static __device__ float g_qkvP[(size_t)3 * BHN * SEQ * HDIM];  // [s][bh][n][d] (tf32-rounded)
static __device__ float g_attn[(size_t)BHN * SEQ * SEQ];       // attnT: [bh][m][n] = e^2 (tf32)
static __device__ float g_vcatR[(size_t)BHN * DD * SEQ];       // [bh][e][n] * rinv[n] (rounded)
static __device__ float g_vcatC[(size_t)BHN * DD * SEQ];       // [bh][e][m] * cinv[m] (rounded)
static __device__ float g_f1  [(size_t)BHN * DD * SEQ];        // [bh][d][m] (rounded)
static __device__ float g_fundT[(size_t)BB * DD * HD3P];       // padded ld (rounded)
static __device__ float g_fsp[(size_t)2 * BHN * DD * DD];      // fund split-K partials
static __device__ float g_osp[(size_t)2 * BB * DD * DIMC];     // out split-K partials
static __device__ float g_xr[(size_t)BB * SEQ * DIMC];         // rounded x
static __device__ float g_wqkvr[(size_t)3 * DIMC * DIMC];      // rounded W_qkv
static __device__ float g_wpfr[(size_t)DIMC * HD3P];           // rounded+padded W_pf
static __device__ float g_rinv[BHN * SEQ];                     // 1/col-sum (per n)
static __device__ float g_cinv[BHN * SEQ];                     // 1/row-sum (per m)
static __device__ float g_csump[(size_t)NPART * BHN * SEQ];    // partial row-sums (per m)
static __device__ float g_rsump[(size_t)NPART * BHN * SEQ];    // partial col-sums (per n)

// ---------------------------------------------------------------------------
// Helpers (plain sm_80-era PTX; nothing "a"-gated)
// ---------------------------------------------------------------------------
__device__ __forceinline__ uint32_t smem_u32(const void* p) {
    uint32_t a;
    asm("{ .reg .u64 t; cvta.to.shared.u64 t, %1; cvt.u32.u64 %0, t; }" : "=r"(a) : "l"(p));
    return a;
}
__device__ __forceinline__ float cvt_tf32(float x) {
    float y; asm("cvt.rna.tf32.f32 %0, %1;" : "=f"(y) : "f"(x)); return y;
}
__device__ __forceinline__ void cp16(uint32_t dst, const void* src, int srcbytes) {
    asm volatile("cp.async.cg.shared.global [%0], [%1], 16, %2;"
                 :: "r"(dst), "l"(src), "r"(srcbytes));
}
__device__ __forceinline__ void cp_commit() { asm volatile("cp.async.commit_group;"); }
__device__ __forceinline__ void cp_wait1()  { asm volatile("cp.async.wait_group 1;"); }
__device__ __forceinline__ void cp_wait0()  { asm volatile("cp.async.wait_group 0;"); }

#define LDSM_X4(r, addr) \
    asm volatile("ldmatrix.sync.aligned.m8n8.x4.shared.b16 {%0,%1,%2,%3}, [%4];" \
        : "=r"((r)[0]), "=r"((r)[1]), "=r"((r)[2]), "=r"((r)[3]) : "r"(addr))

#define MMA_TF32(c, a, b0v, b1v) \
    asm volatile("mma.sync.aligned.m16n8k8.row.col.f32.tf32.tf32.f32 " \
        "{%0,%1,%2,%3}, {%4,%5,%6,%7}, {%8,%9}, {%0,%1,%2,%3};" \
        : "+f"((c)[0]), "+f"((c)[1]), "+f"((c)[2]), "+f"((c)[3]) \
        : "r"((a)[0]), "r"((a)[1]), "r"((a)[2]), "r"((a)[3]), "r"(b0v), "r"(b1v))

// ---------------------------------------------------------------------------
// tf32 tensor-core GEMM, cp.async 3-stage pipeline.
// C[i,j] = alpha * sum_k A(i,k)*B(j,k); operands PRE-ROUNDED to tf32 in gmem.
// CTA tile 128x128, K-tile 32, 256 threads (8 warps, 64Mx32N warptile).
// NS: split-K factor (blockIdx.z = bh*NS + sp; partial C per z when NS>1).
// EPI 0: plain store; EPI 1: QKV scatter;
// EPI 3: store tf32(e^2), e=exp(v*alpha), + per-CTA row/col partial sums of e.
// RND: tf32-round output.
// ---------------------------------------------------------------------------
#define STAGE_STRIDE 32768u
static constexpr unsigned SMEM_TOTAL = 3 * STAGE_STRIDE;   // 96 KB

__device__ __forceinline__ void issue_stage(
    const float* __restrict__ A, const float* __restrict__ B, uint32_t sb, int kt,
    int i0, int j0, int M, int N, int K, int lda, int ldb, int u, int rs)
{
    const uint32_t aB = sb + (uint32_t)(kt % 3) * STAGE_STRIDE;
    const uint32_t bB = aB + 16384u;
    const int kk  = kt * 32 + u * 4;
    const int rem = K - kk;
    const int bytes = rem >= 4 ? 16 : (rem > 0 ? rem * 4 : 0);
    const uint32_t csw = (uint32_t)(u * 16);
#pragma unroll
    for (int it = 0; it < 4; it++) {
        int r = rs + it * 32;
        uint32_t off = (uint32_t)(r * 128) + (csw ^ (uint32_t)((r & 7) << 4));
        int gia = i0 + r, gib = j0 + r;
        const float* pa = A + (long long)(gia < M ? gia : 0) * lda + kk;
        const float* pb = B + (long long)(gib < N ? gib : 0) * ldb + kk;
        cp16(aB + off, pa, gia < M ? bytes : 0);
        cp16(bB + off, pb, gib < N ? bytes : 0);
    }
    cp_commit();
}

template<int EPI, int RND, int NS>
__global__ void __launch_bounds__(256, 2) ca_gemm(
    const float* __restrict__ A, const float* __restrict__ B,
    float* __restrict__ C, const float* __restrict__ bias,
    int M, int N, int K, int lda, int ldb, int ldc,
    long long sA, long long sB, long long sC, float alpha,
    float* __restrict__ csump, float* __restrict__ rsump)
{
    extern __shared__ char smem[];
    const uint32_t sb = smem_u32(smem);

    const int bh = blockIdx.z / NS;
    const int sp = blockIdx.z - bh * NS;
    const int chunk = ((K / NS) + 31) & ~31;
    const int koff  = sp * chunk;
    const int Keff  = (K - koff < chunk) ? (K - koff) : chunk;

    A += (long long)bh * sA + koff;
    B += (long long)bh * sB + koff;
    if (EPI != 1) C += (long long)blockIdx.z * sC;
    const int i0 = blockIdx.y * 128;
    const int j0 = blockIdx.x * 128;

    const int tid  = threadIdx.x;
    const int wid  = tid >> 5, lane = tid & 31;
    const int wm   = wid >> 2, wn = wid & 3;
    const int g    = lane >> 2, tg = lane & 3;
    const int sub  = lane >> 3, l  = lane & 7;
    const int u    = tid & 7,  rs  = tid >> 3;

    const int halfA = sub >> 1;
    const int halfB = sub & 1;
    uint32_t laOff[4], la7[4], lbOff[2], lb7[2];
#pragma unroll
    for (int m = 0; m < 4; m++) {
        int r = wm * 64 + m * 16 + (sub & 1) * 8 + l;
        laOff[m] = (uint32_t)(r * 128); la7[m] = (uint32_t)(r & 7);
    }
#pragma unroll
    for (int p = 0; p < 2; p++) {
        int r = wn * 32 + p * 16 + (sub >> 1) * 8 + l;
        lbOff[p] = (uint32_t)(r * 128); lb7[p] = (uint32_t)(r & 7);
    }

    float acc[4][4][4];
#pragma unroll
    for (int m = 0; m < 4; m++)
#pragma unroll
        for (int n = 0; n < 4; n++)
#pragma unroll
            for (int e = 0; e < 4; e++) acc[m][n][e] = 0.f;

    const int nk = (Keff + 31) / 32;
    issue_stage(A, B, sb, 0, i0, j0, M, N, Keff, lda, ldb, u, rs);
    if (nk > 1) issue_stage(A, B, sb, 1, i0, j0, M, N, Keff, lda, ldb, u, rs);

    for (int kt = 0; kt < nk; kt++) {
        if (kt + 1 < nk) cp_wait1(); else cp_wait0();
        __syncthreads();
        if (kt + 2 < nk)
            issue_stage(A, B, sb, kt + 2, i0, j0, M, N, Keff, lda, ldb, u, rs);

        const uint32_t aB = sb + (uint32_t)(kt % 3) * STAGE_STRIDE;
        const uint32_t bB = aB + 16384u;
#pragma unroll
        for (int ks = 0; ks < 4; ks++) {
            uint32_t af[4][4], bf[2][4];
#pragma unroll
            for (int m = 0; m < 4; m++) {
                uint32_t ch = (uint32_t)(ks * 2 + halfA) ^ la7[m];
                LDSM_X4(af[m], aB + laOff[m] + (ch << 4));
            }
#pragma unroll
            for (int p = 0; p < 2; p++) {
                uint32_t ch = (uint32_t)(ks * 2 + halfB) ^ lb7[p];
                LDSM_X4(bf[p], bB + lbOff[p] + (ch << 4));
            }
#pragma unroll
            for (int m = 0; m < 4; m++) {
#pragma unroll
                for (int n = 0; n < 4; n++)
                    MMA_TF32(acc[m][n], af[m], bf[n >> 1][(n & 1) * 2], bf[n >> 1][(n & 1) * 2 + 1]);
            }
        }
    }

    if (EPI == 3) {
        // ---- softmax-fused epilogue: store tf32(e^2), reduce partial sums of e ----
        __syncthreads();
        float* red = (float*)smem;            // [0:128) row sums, [128:256) col sums
        red[tid] = 0.f;
        __syncthreads();

        float colacc[4][2];
#pragma unroll
        for (int n = 0; n < 4; n++) { colacc[n][0] = 0.f; colacc[n][1] = 0.f; }

#pragma unroll
        for (int m = 0; m < 4; m++) {
            int r0 = i0 + wm * 64 + m * 16 + g;
            float rowacc0 = 0.f, rowacc1 = 0.f;
#pragma unroll
            for (int n = 0; n < 4; n++) {
                int gj = j0 + wn * 32 + n * 8 + 2 * tg;
                float e0 = __expf(acc[m][n][0] * alpha);
                float e1 = __expf(acc[m][n][1] * alpha);
                float e2 = __expf(acc[m][n][2] * alpha);
                float e3 = __expf(acc[m][n][3] * alpha);
                *(float2*)&C[(long long)r0 * ldc + gj] =
                    make_float2(cvt_tf32(e0 * e0), cvt_tf32(e1 * e1));
                *(float2*)&C[(long long)(r0 + 8) * ldc + gj] =
                    make_float2(cvt_tf32(e2 * e2), cvt_tf32(e3 * e3));
                rowacc0 += e0 + e1; rowacc1 += e2 + e3;
                colacc[n][0] += e0 + e2; colacc[n][1] += e1 + e3;
            }
            rowacc0 += __shfl_xor_sync(0xffffffffu, rowacc0, 1);
            rowacc0 += __shfl_xor_sync(0xffffffffu, rowacc0, 2);
            rowacc1 += __shfl_xor_sync(0xffffffffu, rowacc1, 1);
            rowacc1 += __shfl_xor_sync(0xffffffffu, rowacc1, 2);
            if (tg == 0) {
                atomicAdd(&red[wm * 64 + m * 16 + g], rowacc0);
                atomicAdd(&red[wm * 64 + m * 16 + g + 8], rowacc1);
            }
        }
#pragma unroll
        for (int n = 0; n < 4; n++) {
            float c0 = colacc[n][0], c1 = colacc[n][1];
            c0 += __shfl_xor_sync(0xffffffffu, c0, 4);
            c0 += __shfl_xor_sync(0xffffffffu, c0, 8);
            c0 += __shfl_xor_sync(0xffffffffu, c0, 16);
            c1 += __shfl_xor_sync(0xffffffffu, c1, 4);
            c1 += __shfl_xor_sync(0xffffffffu, c1, 8);
            c1 += __shfl_xor_sync(0xffffffffu, c1, 16);
            if (g == 0) {
                atomicAdd(&red[128 + wn * 32 + n * 8 + 2 * tg], c0);
                atomicAdd(&red[128 + wn * 32 + n * 8 + 2 * tg + 1], c1);
            }
        }
        __syncthreads();
        const int S = BHN * SEQ;
        if (tid < 128)
            csump[(long long)blockIdx.x * S + bh * SEQ + i0 + tid] = red[tid];
        else
            rsump[(long long)blockIdx.y * S + bh * SEQ + j0 + (tid - 128)] = red[tid];
        return;
    }

    // ---- standard / scatter epilogues ----
#pragma unroll
    for (int m = 0; m < 4; m++) {
        int r0 = i0 + wm * 64 + m * 16 + g;
#pragma unroll
        for (int n = 0; n < 4; n++) {
            int gj = j0 + wn * 32 + n * 8 + 2 * tg;
            if (gj >= N) continue;
            float2 v0 = make_float2(acc[m][n][0] * alpha, acc[m][n][1] * alpha);
            float2 v1 = make_float2(acc[m][n][2] * alpha, acc[m][n][3] * alpha);
            if (RND) {
                v0.x = cvt_tf32(v0.x); v0.y = cvt_tf32(v0.y);
                v1.x = cvt_tf32(v1.x); v1.y = cvt_tf32(v1.y);
            }
            if (EPI == 1) {
                int s_  = gj / DIMC;
                int rc  = gj - s_ * DIMC;
                int h   = rc >> 8;
                int d   = rc & 255;
#pragma unroll
                for (int hh = 0; hh < 2; hh++) {
                    int gi = r0 + hh * 8;
                    if (gi >= M) continue;
                    int b_ = gi / SEQ, nn = gi - b_ * SEQ;
                    long long dst = ((((long long)s_ * BHN) + (b_ * NH + h)) * SEQ + nn) * HDIM + d;
                    *(float2*)&C[dst] = hh ? v1 : v0;
                }
            } else {
                if (r0 < M)     *(float2*)&C[(long long)r0 * ldc + gj] = v0;
                if (r0 + 8 < M) *(float2*)&C[(long long)(r0 + 8) * ldc + gj] = v1;
            }
        }
    }
}

// ---------------------------------------------------------------------------
// Prep: tf32-round copies of external inputs
// ---------------------------------------------------------------------------
__global__ void round_copy4(const float4* __restrict__ src, float4* __restrict__ dst, int n4)
{
    int i = blockIdx.x * 256 + threadIdx.x;
    if (i >= n4) return;
    float4 v = src[i];
    v.x = cvt_tf32(v.x); v.y = cvt_tf32(v.y); v.z = cvt_tf32(v.z); v.w = cvt_tf32(v.w);
    dst[i] = v;
}

__global__ void pad_round_wpf(const float* __restrict__ W, float* __restrict__ out)
{
    int idx = blockIdx.x * 256 + threadIdx.x;
    if (idx >= DIMC * HD3P) return;
    int o = idx / HD3P, j = idx - o * HD3P;
    out[idx] = (j < HD3) ? cvt_tf32(W[o * HD3 + j]) : 0.f;
}

// ---------------------------------------------------------------------------
// Combine NPART partial sums -> reciprocals (both arrays, one launch)
// ---------------------------------------------------------------------------
__global__ void part_comb2(const float* __restrict__ csump, const float* __restrict__ rsump,
                           float* __restrict__ cinv, float* __restrict__ rinv)
{
    const int idx = blockIdx.x * 256 + threadIdx.x;
    if (idx >= BHN * SEQ) return;
    const float* part = blockIdx.y ? rsump : csump;
    float s = 0.f;
#pragma unroll
    for (int p = 0; p < NPART; p++) s += part[(long long)p * (BHN * SEQ) + idx];
    (blockIdx.y ? rinv : cinv)[idx] = 1.f / s;
}

// ---------------------------------------------------------------------------
// vcatR[bh][d][n] = v[bh][n][d]*rinv[n];  vcatC[bh][d][n] = v[bh][n][d]*cinv[n]
// ---------------------------------------------------------------------------
__global__ void build_vcat2(const float* __restrict__ qkvP,
                            const float* __restrict__ rinv, const float* __restrict__ cinv,
                            float* __restrict__ vcatR, float* __restrict__ vcatC)
{
    __shared__ float t[32][33];
    const int bh = blockIdx.z;
    const int n0 = blockIdx.x * 32;
    const int d0 = blockIdx.y * 32;
    const float* src = qkvP + ((long long)(2 * BHN + bh) * SEQ) * HDIM;
#pragma unroll
    for (int k = 0; k < 4; k++) {
        int n = n0 + threadIdx.y + k * 8;
        t[threadIdx.y + k * 8][threadIdx.x] = src[(long long)n * HDIM + d0 + threadIdx.x];
    }
    __syncthreads();
    const int n = n0 + threadIdx.x;
    const float rs = rinv[bh * SEQ + n];
    const float cs = cinv[bh * SEQ + n];
    float* dR = vcatR + (long long)bh * DD * SEQ;
    float* dC = vcatC + (long long)bh * DD * SEQ;
#pragma unroll
    for (int k = 0; k < 4; k++) {
        int d = d0 + threadIdx.y + k * 8;
        float v = t[threadIdx.x][threadIdx.y + k * 8];
        dR[(long long)d * SEQ + n] = cvt_tf32(v * rs);
        dC[(long long)d * SEQ + n] = cvt_tf32(v * cs);
    }
}

// positional rows e = 256..261 of vcatR/vcatC (scaled per-bh)
__global__ void build_pos2(const float* __restrict__ rinv, const float* __restrict__ cinv,
                           float* __restrict__ vcatR, float* __restrict__ vcatC)
{
    const int n  = blockIdx.x * 256 + threadIdx.x;
    const int bh = blockIdx.y;
    int iy = n % 48;
    int ix = n / 48;
    float y = -1.f + 2.f * (float)iy / 47.f;
    float x = -1.f + 2.f * (float)ix / 63.f;
    float p[6] = { y * y, x * x, y * x, y, x, 1.f };
    const float rs = rinv[bh * SEQ + n];
    const float cs = cinv[bh * SEQ + n];
    float* dR = vcatR + (long long)bh * DD * SEQ + n;
    float* dC = vcatC + (long long)bh * DD * SEQ + n;
#pragma unroll
    for (int j = 0; j < 6; j++) {
        dR[(long long)(HDIM + j) * SEQ] = cvt_tf32(p[j] * rs);
        dC[(long long)(HDIM + j) * SEQ] = cvt_tf32(p[j] * cs);
    }
}

// ---------------------------------------------------------------------------
// f1 positional rows: f1[bh][256+j][m] = sum_n vcatR_pos[bh][j][n] * e2[bh][m][n]
// ---------------------------------------------------------------------------
__global__ void __launch_bounds__(256) f1_pos(
    const float* __restrict__ attnf, const float* __restrict__ vcatR,
    float* __restrict__ f1)
{
    __shared__ float ps[6][1024];
    const int bh  = blockIdx.y;
    const int m0  = blockIdx.x * 32;
    const int tid = threadIdx.x, wid = tid >> 5, lane = tid & 31;

    float acc[4][6];
#pragma unroll
    for (int rr = 0; rr < 4; rr++)
#pragma unroll
        for (int j = 0; j < 6; j++) acc[rr][j] = 0.f;

    const float* pbase = vcatR + ((long long)bh * DD + HDIM) * SEQ;

    for (int c = 0; c < 3; c++) {
        const int n0c = c * 1024;
        __syncthreads();
#pragma unroll
        for (int j = 0; j < 6; j++)
            *(float4*)&ps[j][tid * 4] = *(const float4*)(pbase + (long long)j * SEQ + n0c + tid * 4);
        __syncthreads();
#pragma unroll
        for (int rr = 0; rr < 4; rr++) {
            const int m = m0 + wid * 4 + rr;
            const float* arow = attnf + ((long long)bh * SEQ + m) * SEQ + n0c;
#pragma unroll
            for (int q = 0; q < 8; q++) {
                const int nl = lane * 4 + q * 128;
                float4 a = *(const float4*)(arow + nl);
#pragma unroll
                for (int j = 0; j < 6; j++) {
                    float4 p4 = *(const float4*)&ps[j][nl];
                    acc[rr][j] += a.x * p4.x + a.y * p4.y + a.z * p4.z + a.w * p4.w;
                }
            }
        }
    }
#pragma unroll
    for (int rr = 0; rr < 4; rr++) {
        const int m = m0 + wid * 4 + rr;
#pragma unroll
        for (int j = 0; j < 6; j++) {
            float s = acc[rr][j];
            for (int o = 16; o; o >>= 1) s += __shfl_xor_sync(0xffffffffu, s, o);
            if (lane == 0)
                f1[((long long)bh * DD + HDIM + j) * SEQ + m] = cvt_tf32(s);
        }
    }
}

// ---------------------------------------------------------------------------
// fund split-K combine + transposed scatter: fundT[b][e][h*DD+d]
// ---------------------------------------------------------------------------
__global__ void fund_comb(const float* __restrict__ fsp, float* __restrict__ fundT)
{
    const long long idx = (long long)blockIdx.x * 256 + threadIdx.x;
    if (idx >= (long long)BHN * DD * DD) return;
    const int e  = (int)(idx % DD);
    const long long r = idx / DD;
    const int d  = (int)(r % DD);
    const int bh = (int)(r / DD);
    const int b  = bh / NH;
    const int h  = bh - b * NH;
    const long long off = (long long)d * DD + e;
    float s = fsp[(long long)(bh * 2) * DD * DD + off]
            + fsp[(long long)(bh * 2 + 1) * DD * DD + off];
    fundT[((long long)(b * DD + e)) * HD3P + h * DD + d] = cvt_tf32(s);
}

__global__ void zero_pad_fundT(float* __restrict__ fundT)
{
    const int idx = blockIdx.x * 256 + threadIdx.x;
    if (idx >= BB * DD * 2) return;
    int p = idx & 1, row = idx >> 1;
    fundT[(long long)row * HD3P + HD3 + p] = 0.f;
}

// ---------------------------------------------------------------------------
// out split-K combine + bias
// ---------------------------------------------------------------------------
__global__ void out_comb(const float* __restrict__ osp, const float* __restrict__ bias,
                         float* __restrict__ out)
{
    const long long idx = (long long)blockIdx.x * 256 + threadIdx.x;
    if (idx >= (long long)BB * DD * DIMC) return;
    const int o = (int)(idx % DIMC);
    const long long r = idx / DIMC;
    const int e = (int)(r % DD);
    const int b = (int)(r / DD);
    const long long off = (long long)e * DIMC + o;
    out[idx] = osp[(long long)(b * 2) * DD * DIMC + off]
             + osp[(long long)(b * 2 + 1) * DD * DIMC + off] + bias[o];
}

// ---------------------------------------------------------------------------
// Launch
// ---------------------------------------------------------------------------
extern "C" void kernel_launch(void* const* d_in, const int* in_sizes, int n_in,
                              void* d_out, int out_size)
{
    const float* x    = (const float*)d_in[0];  // [4,3072,768]
    const float* Wqkv = (const float*)d_in[1];  // [2304,768]
    const float* Wpf  = (const float*)d_in[2];  // [768,786]
    const float* bpf  = (const float*)d_in[3];  // [768]
    float* out = (float*)d_out;                 // [4,262,768]

    float *qkvP, *attn, *vcatR, *vcatC, *f1, *fundT, *fsp, *osp, *xr, *wqkvr, *wpfr;
    float *rinv, *cinv, *csump, *rsump;
    cudaGetSymbolAddress((void**)&qkvP,  g_qkvP);
    cudaGetSymbolAddress((void**)&attn,  g_attn);
    cudaGetSymbolAddress((void**)&vcatR, g_vcatR);
    cudaGetSymbolAddress((void**)&vcatC, g_vcatC);
    cudaGetSymbolAddress((void**)&f1,    g_f1);
    cudaGetSymbolAddress((void**)&fundT, g_fundT);
    cudaGetSymbolAddress((void**)&fsp,   g_fsp);
    cudaGetSymbolAddress((void**)&osp,   g_osp);
    cudaGetSymbolAddress((void**)&xr,    g_xr);
    cudaGetSymbolAddress((void**)&wqkvr, g_wqkvr);
    cudaGetSymbolAddress((void**)&wpfr,  g_wpfr);
    cudaGetSymbolAddress((void**)&rinv,  g_rinv);
    cudaGetSymbolAddress((void**)&cinv,  g_cinv);
    cudaGetSymbolAddress((void**)&csump, g_csump);
    cudaGetSymbolAddress((void**)&rsump, g_rsump);

    cudaFuncSetAttribute(ca_gemm<0,1,1>, cudaFuncAttributeMaxDynamicSharedMemorySize, SMEM_TOTAL);
    cudaFuncSetAttribute(ca_gemm<1,1,1>, cudaFuncAttributeMaxDynamicSharedMemorySize, SMEM_TOTAL);
    cudaFuncSetAttribute(ca_gemm<3,0,1>, cudaFuncAttributeMaxDynamicSharedMemorySize, SMEM_TOTAL);
    cudaFuncSetAttribute(ca_gemm<0,0,2>, cudaFuncAttributeMaxDynamicSharedMemorySize, SMEM_TOTAL);

    const long long sQ = (long long)SEQ * HDIM;

    // 0) tf32-round external operands
    round_copy4<<<(BB * SEQ * DIMC / 4 + 255) / 256, 256>>>(
        (const float4*)x, (float4*)xr, BB * SEQ * DIMC / 4);
    round_copy4<<<(3 * DIMC * DIMC / 4 + 255) / 256, 256>>>(
        (const float4*)Wqkv, (float4*)wqkvr, 3 * DIMC * DIMC / 4);
    pad_round_wpf<<<(DIMC * HD3P + 255) / 256, 256>>>(Wpf, wpfr);

    // 1) QKV projection, scattered (rounded) to [s][bh][n][d]
    ca_gemm<1,1,1><<<dim3((3 * DIMC) / 128, (BB * SEQ) / 128, 1), 256, SMEM_TOTAL>>>(
        xr, wqkvr, qkvP, nullptr,
        BB * SEQ, 3 * DIMC, DIMC, DIMC, DIMC, 0, 0, 0, 0, 1.f, nullptr, nullptr);

    // 2) attnT[m][n] = tf32(e^2), e = exp(scale * k_m . q_n); fused partial sums of e
    ca_gemm<3,0,1><<<dim3(SEQ / 128, SEQ / 128, BHN), 256, SMEM_TOTAL>>>(
        qkvP + (long long)BHN * sQ, qkvP, attn, nullptr,
        SEQ, SEQ, HDIM, HDIM, HDIM, SEQ,
        sQ, sQ, (long long)SEQ * SEQ, 0.0625f, csump, rsump);

    // 3) combine partials -> reciprocals (single launch)
    part_comb2<<<dim3((BHN * SEQ + 255) / 256, 2), 256>>>(csump, rsump, cinv, rinv);

    // 4) vcatR/vcatC = scaled transposed v_cat (+ pos rows)
    build_vcat2<<<dim3(SEQ / 32, HDIM / 32, BHN), dim3(32, 8)>>>(qkvP, rinv, cinv, vcatR, vcatC);
    build_pos2<<<dim3(SEQ / 256, BHN), 256>>>(rinv, cinv, vcatR, vcatC);

    // 5) f1 v-rows: f1[d][m] = sum_n vcatR[d][n] * e2[m][n]   (+ pos rows kernel)
    ca_gemm<0,1,1><<<dim3(SEQ / 128, HDIM / 128, BHN), 256, SMEM_TOTAL>>>(
        vcatR, attn, f1, nullptr,
        HDIM, SEQ, SEQ, SEQ, SEQ, SEQ,
        (long long)DD * SEQ, (long long)SEQ * SEQ, (long long)DD * SEQ, 1.f, nullptr, nullptr);
    f1_pos<<<dim3(SEQ / 32, BHN), 256>>>(attn, vcatR, f1);

    // 6) fund split-K x2 -> partials, then combine + scatter into fundT
    ca_gemm<0,0,2><<<dim3((DD + 127) / 128, (DD + 127) / 128, BHN * 2), 256, SMEM_TOTAL>>>(
        f1, vcatC, fsp, nullptr,
        DD, DD, SEQ, SEQ, SEQ, DD,
        (long long)DD * SEQ, (long long)DD * SEQ, (long long)DD * DD, 1.f, nullptr, nullptr);
    fund_comb<<<(int)(((long long)BHN * DD * DD + 255) / 256), 256>>>(fsp, fundT);
    zero_pad_fundT<<<(BB * DD * 2 + 255) / 256, 256>>>(fundT);

    // 7) out split-K x2 -> partials, then combine + bias
    ca_gemm<0,0,2><<<dim3(DIMC / 128, (DD + 127) / 128, BB * 2), 256, SMEM_TOTAL>>>(
        fundT, wpfr, osp, nullptr,
        DD, DIMC, HD3, HD3P, HD3P, DIMC,
        (long long)DD * HD3P, 0, (long long)DD * DIMC, 1.f, nullptr, nullptr);
    out_comb<<<(int)(((long long)BB * DD * DIMC + 255) / 256), 256>>>(osp, bpf, out);
}